// round 7
// baseline (speedup 1.0000x reference)
#include <cuda_runtime.h>

#define Bq  256
#define Tq  2000
#define Fq  80
#define Hq  64
#define G3q 192
#define Oq  29

// Precomputed layer-0 input projection: gx0[b][t][g] (393 MB static device scratch)
__device__ float g_gx0[(size_t)Bq * Tq * G3q];

// MUFU.TANH (sm_75+)
__device__ __forceinline__ float tanha(float x) {
    float y;
    asm("tanh.approx.f32 %0, %1;" : "=f"(y) : "f"(x));
    return y;
}
__device__ __forceinline__ float siga(float x) {
    return fmaf(tanha(0.5f * x), 0.5f, 0.5f);
}

// Blackwell packed f32x2 FMA (PTX-only; ptxas never auto-fuses)
__device__ __forceinline__ float2 ffma2(float2 a, float2 b, float2 c) {
    float2 d;
    asm("fma.rn.f32x2 %0, %1, %2, %3;"
        : "=l"(*reinterpret_cast<unsigned long long*>(&d))
        : "l"(*reinterpret_cast<unsigned long long*>(&a)),
          "l"(*reinterpret_cast<unsigned long long*>(&b)),
          "l"(*reinterpret_cast<unsigned long long*>(&c)));
    return d;
}

// ---------------------------------------------------------------------------
// Kernel 1: gx0 = x @ W_ih0^T + b_ih0   (time-parallel GEMM, t-pair f32x2)
// grid = 512 (256 batches x 2 T-halves); block = 192 threads (1 thread = 1 gate)
// Each block: 25 chunks of 40 timesteps; per f: 1 w-LDS + 10 x-LDS.128 + 20 ffma2.
// ---------------------------------------------------------------------------
__global__ __launch_bounds__(192) void gx0_kernel(
    const float* __restrict__ x,
    const float* __restrict__ W_ih0,
    const float* __restrict__ b_ih0)
{
    extern __shared__ float sm[];
    float* Wsh = sm;               // [80][192]  W_ih0 transposed
    float* bsh = Wsh + Fq * G3q;   // [192]
    float* xs  = bsh + G3q;        // [80][40]   x tile transposed

    const int tid    = threadIdx.x;
    const int b      = blockIdx.x >> 1;
    const int t0base = (blockIdx.x & 1) * 1000;

    for (int idx = tid; idx < G3q * Fq; idx += 192) {
        int gg = idx / Fq, f = idx % Fq;
        Wsh[f * G3q + gg] = W_ih0[idx];
    }
    if (tid < G3q) bsh[tid] = b_ih0[tid];
    __syncthreads();

    const int g = tid;
    for (int c = 0; c < 25; ++c) {
        int t0 = t0base + c * 40;
        for (int idx = tid; idx < 40 * Fq; idx += 192) {
            int tt = idx / Fq, f = idx % Fq;
            xs[f * 40 + tt] = x[((size_t)b * Tq + t0 + tt) * Fq + f];
        }
        __syncthreads();

        float2 acc[20];                 // 20 time-pairs (40 t)
        float bias = bsh[g];
        #pragma unroll
        for (int i = 0; i < 20; ++i) acc[i] = make_float2(bias, bias);

        #pragma unroll 2
        for (int f = 0; f < Fq; ++f) {
            float w = Wsh[f * G3q + g];
            float2 w2 = make_float2(w, w);
            const float4* xv = reinterpret_cast<const float4*>(&xs[f * 40]);
            #pragma unroll
            for (int q = 0; q < 10; ++q) {
                float4 v = xv[q];
                acc[q * 2 + 0] = ffma2(w2, make_float2(v.x, v.y), acc[q * 2 + 0]);
                acc[q * 2 + 1] = ffma2(w2, make_float2(v.z, v.w), acc[q * 2 + 1]);
            }
        }
        #pragma unroll
        for (int i = 0; i < 20; ++i) {
            g_gx0[((size_t)b * Tq + t0 + 2 * i + 0) * G3q + g] = acc[i].x;
            g_gx0[((size_t)b * Tq + t0 + 2 * i + 1) * G3q + g] = acc[i].y;
        }
        __syncthreads();
    }
}

// ---------------------------------------------------------------------------
// Kernel 2: fused 2-layer GRU + FC (unchanged R6 structure; L1 reduction now
// 12 shfl: round 1 combines within x/h side, round 2 sums r/z across sides
// and exchanges the opposite side's n-dot).
//   tid   0..127: L0, j = tid>>1, seg = tid&1  (K half; act batch = seg)
//   tid 128..383: L1, j = (tid-128)>>2, seg = (tid-128)&3 (concat quarter)
// ---------------------------------------------------------------------------
__global__ __launch_bounds__(384, 1) void rnn_kernel(
    const float* __restrict__ h_in,
    const float* __restrict__ W_hh0, const float* __restrict__ b_hh0,
    const float* __restrict__ W_ih1, const float* __restrict__ W_hh1,
    const float* __restrict__ b_ih1, const float* __restrict__ b_hh1,
    const float* __restrict__ W_fc,  const float* __restrict__ b_fc,
    float* __restrict__ out, int write_hidden)
{
    // [parity][batch][quarter of concat [h0;h1]][32 + 8 pad]
    __shared__ float hbuf[2][2][4][40];

    const int tid  = threadIdx.x;
    const int b0   = blockIdx.x * 2;
    const bool isL0 = tid < 128;
    int j, seg;
    if (isL0) { j = tid >> 1; seg = tid & 1; }
    else      { int t = tid - 128; j = t >> 2; seg = t & 3; }

    // --- weight rows (r,z,n) for this thread's K window -> registers ---
    float4 wR[8], wZ[8], wN[8];
    {
        const float4* W;
        int k0;
        if (isL0)          { W = (const float4*)W_hh0; k0 = seg * 8; }
        else if (seg < 2)  { W = (const float4*)W_ih1; k0 = seg * 8; }
        else               { W = (const float4*)W_hh1; k0 = (seg - 2) * 8; }
        #pragma unroll
        for (int k = 0; k < 8; ++k) {
            wR[k] = W[(j      ) * 16 + k0 + k];
            wZ[k] = W[(64 + j ) * 16 + k0 + k];
            wN[k] = W[(128 + j) * 16 + k0 + k];
        }
    }
    // --- biases (act role) ---
    float bR, bZ, bNi = 0.0f, bNh;
    if (isL0) {
        bR = b_hh0[j]; bZ = b_hh0[64 + j]; bNh = b_hh0[128 + j];
    } else {
        bR  = b_ih1[j] + b_hh1[j];
        bZ  = b_ih1[64 + j] + b_hh1[64 + j];
        bNi = b_ih1[128 + j]; bNh = b_hh1[128 + j];
    }

    // --- init state: h0^0 -> buf0 q0/q1 ; h1^0 -> buf1 q2/q3 ; rest zero ---
    if (tid < 256) {
        int b = tid >> 7, idx = tid & 127;
        if (idx < 64) {
            hbuf[0][b][idx >> 5][idx & 31] = h_in[(b0 + b) * Hq + idx];
            hbuf[1][b][idx >> 5][idx & 31] = 0.0f;
        } else {
            int jj = idx - 64;
            hbuf[1][b][2 + (jj >> 5)][jj & 31] = h_in[Bq * Hq + (b0 + b) * Hq + jj];
            hbuf[0][b][2 + (jj >> 5)][jj & 31] = 0.0f;
        }
    }
    __syncthreads();

    // gx stream (L0 act role: batch = seg)
    const float* gxp = g_gx0 + (size_t)(b0 + (isL0 ? seg : 0)) * Tq * G3q;
    float gxR = 0.0f, gxZ = 0.0f, gxN = 0.0f;
    if (isL0) { gxR = gxp[j]; gxZ = gxp[64 + j]; gxN = gxp[128 + j]; }

    // previous h element owned by this act thread
    float hprev = 0.0f;
    if (isL0)          hprev = h_in[(b0 + seg) * Hq + j];
    else if (seg < 2)  hprev = h_in[Bq * Hq + (b0 + seg) * Hq + j];

    for (int i = 0; i <= Tq; ++i) {
        const int p = i & 1;

        // prefetch next step's gx (hidden behind the whole step)
        float nR = 0.0f, nZ = 0.0f, nN = 0.0f;
        if (isL0 && i + 1 < Tq) {
            const float* gq = gxp + (size_t)(i + 1) * G3q;
            nR = __ldg(gq + j); nZ = __ldg(gq + 64 + j); nN = __ldg(gq + 128 + j);
        }

        // --- partial dots over this thread's K window, both batches ---
        const float4* u4 = (const float4*)hbuf[p][0][seg];
        const float4* v4 = (const float4*)hbuf[p][1][seg];
        float2 aR0 = {0,0}, aZ0 = {0,0}, aN0 = {0,0};
        float2 aR1 = {0,0}, aZ1 = {0,0}, aN1 = {0,0};
        #pragma unroll
        for (int k = 0; k < 8; ++k) {
            float4 u = u4[k], v = v4[k];
            float2 ulo = make_float2(u.x, u.y), uhi = make_float2(u.z, u.w);
            float2 vlo = make_float2(v.x, v.y), vhi = make_float2(v.z, v.w);
            float2 rlo = make_float2(wR[k].x, wR[k].y), rhi = make_float2(wR[k].z, wR[k].w);
            float2 zlo = make_float2(wZ[k].x, wZ[k].y), zhi = make_float2(wZ[k].z, wZ[k].w);
            float2 nlo = make_float2(wN[k].x, wN[k].y), nhi = make_float2(wN[k].z, wN[k].w);
            aR0 = ffma2(rlo, ulo, aR0);  aR0 = ffma2(rhi, uhi, aR0);
            aZ0 = ffma2(zlo, ulo, aZ0);  aZ0 = ffma2(zhi, uhi, aZ0);
            aN0 = ffma2(nlo, ulo, aN0);  aN0 = ffma2(nhi, uhi, aN0);
            aR1 = ffma2(rlo, vlo, aR1);  aR1 = ffma2(rhi, vhi, aR1);
            aZ1 = ffma2(zlo, vlo, aZ1);  aZ1 = ffma2(zhi, vhi, aZ1);
            aN1 = ffma2(nlo, vlo, aN1);  aN1 = ffma2(nhi, vhi, aN1);
        }
        float dR0 = aR0.x + aR0.y, dZ0 = aZ0.x + aZ0.y, dN0 = aN0.x + aN0.y;
        float dR1 = aR1.x + aR1.y, dZ1 = aZ1.x + aZ1.y, dN1 = aN1.x + aN1.y;

        if (isL0) {
            // 2-way butterfly; then local act + h0 update (owner keeps hprev)
            dR0 += __shfl_xor_sync(0xffffffffu, dR0, 1);
            dZ0 += __shfl_xor_sync(0xffffffffu, dZ0, 1);
            dN0 += __shfl_xor_sync(0xffffffffu, dN0, 1);
            dR1 += __shfl_xor_sync(0xffffffffu, dR1, 1);
            dZ1 += __shfl_xor_sync(0xffffffffu, dZ1, 1);
            dN1 += __shfl_xor_sync(0xffffffffu, dN1, 1);
            if (i < Tq) {
                float dR = seg ? dR1 : dR0;
                float dZ = seg ? dZ1 : dZ0;
                float dN = seg ? dN1 : dN0;
                float r = siga(gxR + dR + bR);
                float z = siga(gxZ + dZ + bZ);
                float n = tanha(fmaf(r, dN + bNh, gxN));   // gxN includes b_ih0
                float hn = (1.0f - z) * n + z * hprev;
                hprev = hn;
                hbuf[p ^ 1][seg][j >> 5][j & 31] = hn;
            }
            gxR = nR; gxZ = nZ; gxN = nN;
        } else {
            // round 1 (xor 1): combine within side (segs {0,1} x-side, {2,3} h-side)
            dR0 += __shfl_xor_sync(0xffffffffu, dR0, 1);
            dZ0 += __shfl_xor_sync(0xffffffffu, dZ0, 1);
            dN0 += __shfl_xor_sync(0xffffffffu, dN0, 1);
            dR1 += __shfl_xor_sync(0xffffffffu, dR1, 1);
            dZ1 += __shfl_xor_sync(0xffffffffu, dZ1, 1);
            dN1 += __shfl_xor_sync(0xffffffffu, dN1, 1);
            // round 2 (xor 2): sum r/z across sides; exchange opposite n-dot
            float oR0 = __shfl_xor_sync(0xffffffffu, dR0, 2);
            float oZ0 = __shfl_xor_sync(0xffffffffu, dZ0, 2);
            float oN0 = __shfl_xor_sync(0xffffffffu, dN0, 2);
            float oR1 = __shfl_xor_sync(0xffffffffu, dR1, 2);
            float oZ1 = __shfl_xor_sync(0xffffffffu, dZ1, 2);
            float oN1 = __shfl_xor_sync(0xffffffffu, dN1, 2);
            dR0 += oR0; dZ0 += oZ0;
            dR1 += oR1; dZ1 += oZ1;
            // seg<2: dN = x-side, oN = h-side
            if (i > 0 && seg < 2) {
                float dR  = seg ? dR1 : dR0;
                float dZ  = seg ? dZ1 : dZ0;
                float dNx = seg ? dN1 : dN0;
                float dNh = seg ? oN1 : oN0;
                float r = siga(dR + bR);
                float z = siga(dZ + bZ);
                float n = tanha(fmaf(r, dNh + bNh, dNx + bNi));
                float hn = (1.0f - z) * n + z * hprev;
                hprev = hn;
                hbuf[p ^ 1][seg][2 + (j >> 5)][j & 31] = hn;
            }
        }
        __syncthreads();   // publish h0^{i+1}, h1^{i} for next iteration
    }

    // ---- epilogue: h0 final in buf0 q0/q1, h1 final in buf1 q2/q3 ----
    if (write_hidden && tid < 2 * Hq) {
        int b = tid >> 6, jj = tid & 63;
        out[Bq * Oq + (b0 + b) * Hq + jj]           = hbuf[0][b][jj >> 5][jj & 31];
        out[Bq * Oq + Bq * Hq + (b0 + b) * Hq + jj] = hbuf[1][b][2 + (jj >> 5)][jj & 31];
    }
    if (tid < 2 * Oq) {
        int b = tid / Oq, o = tid - b * Oq;
        float acc = b_fc[o];
        #pragma unroll
        for (int jj = 0; jj < Hq; ++jj)
            acc = fmaf(fmaxf(hbuf[1][b][2 + (jj >> 5)][jj & 31], 0.0f),
                       __ldg(&W_fc[o * Hq + jj]), acc);
        out[(b0 + b) * Oq + o] = acc;
    }
}

// ---------------------------------------------------------------------------
extern "C" void kernel_launch(void* const* d_in, const int* in_sizes, int n_in,
                              void* d_out, int out_size) {
    const float* x     = (const float*)d_in[0];
    const float* h     = (const float*)d_in[1];
    const float* W_ih0 = (const float*)d_in[2];
    const float* W_hh0 = (const float*)d_in[3];
    const float* b_ih0 = (const float*)d_in[4];
    const float* b_hh0 = (const float*)d_in[5];
    const float* W_ih1 = (const float*)d_in[6];
    const float* W_hh1 = (const float*)d_in[7];
    const float* b_ih1 = (const float*)d_in[8];
    const float* b_hh1 = (const float*)d_in[9];
    const float* W_fc  = (const float*)d_in[10];
    const float* b_fc  = (const float*)d_in[11];
    float* out = (float*)d_out;

    const int smem1 = (Fq * G3q + G3q + Fq * 40) * (int)sizeof(float);  // 75,008 B
    cudaFuncSetAttribute(gx0_kernel, cudaFuncAttributeMaxDynamicSharedMemorySize, smem1);

    gx0_kernel<<<Bq * 2, 192, smem1>>>(x, W_ih0, b_ih0);

    int write_hidden = (out_size >= Bq * Oq + 2 * Bq * Hq) ? 1 : 0;
    rnn_kernel<<<Bq / 2, 384>>>(h, W_hh0, b_hh0,
                                W_ih1, W_hh1, b_ih1, b_hh1,
                                W_fc, b_fc, out, write_hidden);
}

// round 9
// speedup vs baseline: 1.1332x; 1.1332x over previous
#include <cuda_runtime.h>

#define Bq  256
#define Tq  2000
#define Fq  80
#define Hq  64
#define G3q 192
#define Oq  29

// Precomputed layer-0 input projection: gx0[b][t][g] (393 MB static device scratch)
__device__ float g_gx0[(size_t)Bq * Tq * G3q];

// MUFU.TANH (sm_75+)
__device__ __forceinline__ float tanha(float x) {
    float y;
    asm("tanh.approx.f32 %0, %1;" : "=f"(y) : "f"(x));
    return y;
}
__device__ __forceinline__ float siga(float x) {
    return fmaf(tanha(0.5f * x), 0.5f, 0.5f);
}

// Blackwell packed f32x2 FMA (PTX-only; ptxas never auto-fuses)
__device__ __forceinline__ float2 ffma2(float2 a, float2 b, float2 c) {
    float2 d;
    asm("fma.rn.f32x2 %0, %1, %2, %3;"
        : "=l"(*reinterpret_cast<unsigned long long*>(&d))
        : "l"(*reinterpret_cast<unsigned long long*>(&a)),
          "l"(*reinterpret_cast<unsigned long long*>(&b)),
          "l"(*reinterpret_cast<unsigned long long*>(&c)));
    return d;
}

// ---------------------------------------------------------------------------
// Kernel 1: gx0 = x @ W_ih0^T + b_ih0.
// grid = 256 (1 block per batch), block = 192 (1 thread = 1 gate).
// Each thread holds its 80-float weight row in 40 float2 REGISTERS (f-paired).
// x chunk (40 t x 80 f, natural layout) staged in SMEM; inner loop processes
// 4 timesteps concurrently: 80 broadcast LDS.128 + 160 ffma2 per group.
// ---------------------------------------------------------------------------
__global__ __launch_bounds__(192, 2) void gx0_kernel(
    const float* __restrict__ x,
    const float* __restrict__ W_ih0,
    const float* __restrict__ b_ih0)
{
    __shared__ float xs[40 * Fq];          // 12.8 KB, [t][f] natural layout

    const int g = threadIdx.x;             // gate 0..191
    const int b = blockIdx.x;              // batch

    // weight row -> registers, f-paired
    float2 wv[40];
    {
        const float2* Wp = reinterpret_cast<const float2*>(W_ih0 + g * Fq);
        #pragma unroll
        for (int k = 0; k < 40; ++k) wv[k] = Wp[k];
    }
    const float bias = b_ih0[g];

    const float4* xg = reinterpret_cast<const float4*>(x + (size_t)b * Tq * Fq);
    float* outp = g_gx0 + (size_t)b * Tq * G3q + g;

    for (int c = 0; c < 50; ++c) {         // 50 chunks x 40 t
        // stage x chunk: 3200 floats = 800 float4, coalesced
        const float4* src = xg + c * (40 * Fq / 4);
        #pragma unroll 1
        for (int i = g; i < 800; i += 192)
            reinterpret_cast<float4*>(xs)[i] = src[i];
        __syncthreads();

        #pragma unroll 1
        for (int tg = 0; tg < 10; ++tg) {  // groups of 4 timesteps
            const float4* x0 = reinterpret_cast<const float4*>(&xs[(tg * 4 + 0) * Fq]);
            const float4* x1 = reinterpret_cast<const float4*>(&xs[(tg * 4 + 1) * Fq]);
            const float4* x2 = reinterpret_cast<const float4*>(&xs[(tg * 4 + 2) * Fq]);
            const float4* x3 = reinterpret_cast<const float4*>(&xs[(tg * 4 + 3) * Fq]);
            float2 a0 = make_float2(bias, 0.0f);
            float2 a1 = make_float2(bias, 0.0f);
            float2 a2 = make_float2(bias, 0.0f);
            float2 a3 = make_float2(bias, 0.0f);
            #pragma unroll
            for (int k = 0; k < 20; ++k) {
                float2 wlo = wv[2 * k], whi = wv[2 * k + 1];
                float4 v0 = x0[k];
                a0 = ffma2(wlo, make_float2(v0.x, v0.y), a0);
                a0 = ffma2(whi, make_float2(v0.z, v0.w), a0);
                float4 v1 = x1[k];
                a1 = ffma2(wlo, make_float2(v1.x, v1.y), a1);
                a1 = ffma2(whi, make_float2(v1.z, v1.w), a1);
                float4 v2 = x2[k];
                a2 = ffma2(wlo, make_float2(v2.x, v2.y), a2);
                a2 = ffma2(whi, make_float2(v2.z, v2.w), a2);
                float4 v3 = x3[k];
                a3 = ffma2(wlo, make_float2(v3.x, v3.y), a3);
                a3 = ffma2(whi, make_float2(v3.z, v3.w), a3);
            }
            int tbase = c * 40 + tg * 4;
            outp[(size_t)(tbase + 0) * G3q] = a0.x + a0.y;
            outp[(size_t)(tbase + 1) * G3q] = a1.x + a1.y;
            outp[(size_t)(tbase + 2) * G3q] = a2.x + a2.y;
            outp[(size_t)(tbase + 3) * G3q] = a3.x + a3.y;
        }
        __syncthreads();
    }
}

// ---------------------------------------------------------------------------
// Kernel 2: fused 2-layer GRU + FC (identical to R7: gate-owner threads,
// register weights, shfl reduction, one __syncthreads per step).
//   tid   0..127: L0, j = tid>>1, seg = tid&1  (K half; act batch = seg)
//   tid 128..383: L1, j = (tid-128)>>2, seg = (tid-128)&3 (concat quarter)
// ---------------------------------------------------------------------------
__global__ __launch_bounds__(384, 1) void rnn_kernel(
    const float* __restrict__ h_in,
    const float* __restrict__ W_hh0, const float* __restrict__ b_hh0,
    const float* __restrict__ W_ih1, const float* __restrict__ W_hh1,
    const float* __restrict__ b_ih1, const float* __restrict__ b_hh1,
    const float* __restrict__ W_fc,  const float* __restrict__ b_fc,
    float* __restrict__ out, int write_hidden)
{
    // [parity][batch][quarter of concat [h0;h1]][32 + 8 pad]
    __shared__ float hbuf[2][2][4][40];

    const int tid  = threadIdx.x;
    const int b0   = blockIdx.x * 2;
    const bool isL0 = tid < 128;
    int j, seg;
    if (isL0) { j = tid >> 1; seg = tid & 1; }
    else      { int t = tid - 128; j = t >> 2; seg = t & 3; }

    // --- weight rows (r,z,n) for this thread's K window -> registers ---
    float4 wR[8], wZ[8], wN[8];
    {
        const float4* W;
        int k0;
        if (isL0)          { W = (const float4*)W_hh0; k0 = seg * 8; }
        else if (seg < 2)  { W = (const float4*)W_ih1; k0 = seg * 8; }
        else               { W = (const float4*)W_hh1; k0 = (seg - 2) * 8; }
        #pragma unroll
        for (int k = 0; k < 8; ++k) {
            wR[k] = W[(j      ) * 16 + k0 + k];
            wZ[k] = W[(64 + j ) * 16 + k0 + k];
            wN[k] = W[(128 + j) * 16 + k0 + k];
        }
    }
    // --- biases (act role) ---
    float bR, bZ, bNi = 0.0f, bNh;
    if (isL0) {
        bR = b_hh0[j]; bZ = b_hh0[64 + j]; bNh = b_hh0[128 + j];
    } else {
        bR  = b_ih1[j] + b_hh1[j];
        bZ  = b_ih1[64 + j] + b_hh1[64 + j];
        bNi = b_ih1[128 + j]; bNh = b_hh1[128 + j];
    }

    // --- init state: h0^0 -> buf0 q0/q1 ; h1^0 -> buf1 q2/q3 ; rest zero ---
    if (tid < 256) {
        int b = tid >> 7, idx = tid & 127;
        if (idx < 64) {
            hbuf[0][b][idx >> 5][idx & 31] = h_in[(b0 + b) * Hq + idx];
            hbuf[1][b][idx >> 5][idx & 31] = 0.0f;
        } else {
            int jj = idx - 64;
            hbuf[1][b][2 + (jj >> 5)][jj & 31] = h_in[Bq * Hq + (b0 + b) * Hq + jj];
            hbuf[0][b][2 + (jj >> 5)][jj & 31] = 0.0f;
        }
    }
    __syncthreads();

    // gx stream (L0 act role: batch = seg)
    const float* gxp = g_gx0 + (size_t)(b0 + (isL0 ? seg : 0)) * Tq * G3q;
    float gxR = 0.0f, gxZ = 0.0f, gxN = 0.0f;
    if (isL0) { gxR = gxp[j]; gxZ = gxp[64 + j]; gxN = gxp[128 + j]; }

    // previous h element owned by this act thread
    float hprev = 0.0f;
    if (isL0)          hprev = h_in[(b0 + seg) * Hq + j];
    else if (seg < 2)  hprev = h_in[Bq * Hq + (b0 + seg) * Hq + j];

    for (int i = 0; i <= Tq; ++i) {
        const int p = i & 1;

        // prefetch next step's gx (hidden behind the whole step)
        float nR = 0.0f, nZ = 0.0f, nN = 0.0f;
        if (isL0 && i + 1 < Tq) {
            const float* gq = gxp + (size_t)(i + 1) * G3q;
            nR = __ldg(gq + j); nZ = __ldg(gq + 64 + j); nN = __ldg(gq + 128 + j);
        }

        // --- partial dots over this thread's K window, both batches ---
        const float4* u4 = (const float4*)hbuf[p][0][seg];
        const float4* v4 = (const float4*)hbuf[p][1][seg];
        float2 aR0 = {0,0}, aZ0 = {0,0}, aN0 = {0,0};
        float2 aR1 = {0,0}, aZ1 = {0,0}, aN1 = {0,0};
        #pragma unroll
        for (int k = 0; k < 8; ++k) {
            float4 u = u4[k], v = v4[k];
            float2 ulo = make_float2(u.x, u.y), uhi = make_float2(u.z, u.w);
            float2 vlo = make_float2(v.x, v.y), vhi = make_float2(v.z, v.w);
            float2 rlo = make_float2(wR[k].x, wR[k].y), rhi = make_float2(wR[k].z, wR[k].w);
            float2 zlo = make_float2(wZ[k].x, wZ[k].y), zhi = make_float2(wZ[k].z, wZ[k].w);
            float2 nlo = make_float2(wN[k].x, wN[k].y), nhi = make_float2(wN[k].z, wN[k].w);
            aR0 = ffma2(rlo, ulo, aR0);  aR0 = ffma2(rhi, uhi, aR0);
            aZ0 = ffma2(zlo, ulo, aZ0);  aZ0 = ffma2(zhi, uhi, aZ0);
            aN0 = ffma2(nlo, ulo, aN0);  aN0 = ffma2(nhi, uhi, aN0);
            aR1 = ffma2(rlo, vlo, aR1);  aR1 = ffma2(rhi, vhi, aR1);
            aZ1 = ffma2(zlo, vlo, aZ1);  aZ1 = ffma2(zhi, vhi, aZ1);
            aN1 = ffma2(nlo, vlo, aN1);  aN1 = ffma2(nhi, vhi, aN1);
        }
        float dR0 = aR0.x + aR0.y, dZ0 = aZ0.x + aZ0.y, dN0 = aN0.x + aN0.y;
        float dR1 = aR1.x + aR1.y, dZ1 = aZ1.x + aZ1.y, dN1 = aN1.x + aN1.y;

        if (isL0) {
            // 2-way butterfly; then local act + h0 update (owner keeps hprev)
            dR0 += __shfl_xor_sync(0xffffffffu, dR0, 1);
            dZ0 += __shfl_xor_sync(0xffffffffu, dZ0, 1);
            dN0 += __shfl_xor_sync(0xffffffffu, dN0, 1);
            dR1 += __shfl_xor_sync(0xffffffffu, dR1, 1);
            dZ1 += __shfl_xor_sync(0xffffffffu, dZ1, 1);
            dN1 += __shfl_xor_sync(0xffffffffu, dN1, 1);
            if (i < Tq) {
                float dR = seg ? dR1 : dR0;
                float dZ = seg ? dZ1 : dZ0;
                float dN = seg ? dN1 : dN0;
                float r = siga(gxR + dR + bR);
                float z = siga(gxZ + dZ + bZ);
                float n = tanha(fmaf(r, dN + bNh, gxN));   // gxN includes b_ih0
                float hn = (1.0f - z) * n + z * hprev;
                hprev = hn;
                hbuf[p ^ 1][seg][j >> 5][j & 31] = hn;
            }
            gxR = nR; gxZ = nZ; gxN = nN;
        } else {
            // round 1 (xor 1): combine within side (segs {0,1} x-side, {2,3} h-side)
            dR0 += __shfl_xor_sync(0xffffffffu, dR0, 1);
            dZ0 += __shfl_xor_sync(0xffffffffu, dZ0, 1);
            dN0 += __shfl_xor_sync(0xffffffffu, dN0, 1);
            dR1 += __shfl_xor_sync(0xffffffffu, dR1, 1);
            dZ1 += __shfl_xor_sync(0xffffffffu, dZ1, 1);
            dN1 += __shfl_xor_sync(0xffffffffu, dN1, 1);
            // round 2 (xor 2): sum r/z across sides; exchange opposite n-dot
            float oR0 = __shfl_xor_sync(0xffffffffu, dR0, 2);
            float oZ0 = __shfl_xor_sync(0xffffffffu, dZ0, 2);
            float oN0 = __shfl_xor_sync(0xffffffffu, dN0, 2);
            float oR1 = __shfl_xor_sync(0xffffffffu, dR1, 2);
            float oZ1 = __shfl_xor_sync(0xffffffffu, dZ1, 2);
            float oN1 = __shfl_xor_sync(0xffffffffu, dN1, 2);
            dR0 += oR0; dZ0 += oZ0;
            dR1 += oR1; dZ1 += oZ1;
            // seg<2: dN = x-side, oN = h-side
            if (i > 0 && seg < 2) {
                float dR  = seg ? dR1 : dR0;
                float dZ  = seg ? dZ1 : dZ0;
                float dNx = seg ? dN1 : dN0;
                float dNh = seg ? oN1 : oN0;
                float r = siga(dR + bR);
                float z = siga(dZ + bZ);
                float n = tanha(fmaf(r, dNh + bNh, dNx + bNi));
                float hn = (1.0f - z) * n + z * hprev;
                hprev = hn;
                hbuf[p ^ 1][seg][2 + (j >> 5)][j & 31] = hn;
            }
        }
        __syncthreads();   // publish h0^{i+1}, h1^{i} for next iteration
    }

    // ---- epilogue: h0 final in buf0 q0/q1, h1 final in buf1 q2/q3 ----
    if (write_hidden && tid < 2 * Hq) {
        int b = tid >> 6, jj = tid & 63;
        out[Bq * Oq + (b0 + b) * Hq + jj]           = hbuf[0][b][jj >> 5][jj & 31];
        out[Bq * Oq + Bq * Hq + (b0 + b) * Hq + jj] = hbuf[1][b][2 + (jj >> 5)][jj & 31];
    }
    if (tid < 2 * Oq) {
        int b = tid / Oq, o = tid - b * Oq;
        float acc = b_fc[o];
        #pragma unroll
        for (int jj = 0; jj < Hq; ++jj)
            acc = fmaf(fmaxf(hbuf[1][b][2 + (jj >> 5)][jj & 31], 0.0f),
                       __ldg(&W_fc[o * Hq + jj]), acc);
        out[(b0 + b) * Oq + o] = acc;
    }
}

// ---------------------------------------------------------------------------
extern "C" void kernel_launch(void* const* d_in, const int* in_sizes, int n_in,
                              void* d_out, int out_size) {
    const float* x     = (const float*)d_in[0];
    const float* h     = (const float*)d_in[1];
    const float* W_ih0 = (const float*)d_in[2];
    const float* W_hh0 = (const float*)d_in[3];
    const float* b_ih0 = (const float*)d_in[4];
    const float* b_hh0 = (const float*)d_in[5];
    const float* W_ih1 = (const float*)d_in[6];
    const float* W_hh1 = (const float*)d_in[7];
    const float* b_ih1 = (const float*)d_in[8];
    const float* b_hh1 = (const float*)d_in[9];
    const float* W_fc  = (const float*)d_in[10];
    const float* b_fc  = (const float*)d_in[11];
    float* out = (float*)d_out;

    gx0_kernel<<<Bq, 192>>>(x, W_ih0, b_ih0);

    int write_hidden = (out_size >= Bq * Oq + 2 * Bq * Hq) ? 1 : 0;
    rnn_kernel<<<Bq / 2, 384>>>(h, W_hh0, b_hh0,
                                W_ih1, W_hh1, b_ih1, b_hh1,
                                W_fc, b_fc, out, write_hidden);
}